// round 14
// baseline (speedup 1.0000x reference)
#include <cuda_runtime.h>
#include <math.h>

#define NRAYS   10000
#define NSTEPS  768
#define Zn      32
#define Yn      512
#define Xn      512
#define WPB     8                        // warps per block
#define NBLK    1184                     // 148 SMs * 8 CTAs/SM -> EXACTLY one wave
#define GW      (NBLK * WPB)             // 9472 warps

// Per-block partial sums [l1, l2, absrel]. Every block writes its slot each
// launch before any reader -> no init needed.
__device__ float    g_partials[NBLK * 3];
__device__ unsigned g_count = 0;         // reset by the last block each launch

__global__ void __launch_bounds__(WPB * 32)
ray_march_kernel(const float* __restrict__ grid,     // [5,32,512,512] (T,Z,Y,X)
                 const float* __restrict__ origin,   // [5,3]
                 const float* __restrict__ pts,      // [NRAYS,3]
                 const int*   __restrict__ tindex,   // [NRAYS]
                 float*       __restrict__ out)      // [3]
{
    const int warp = threadIdx.x >> 5;
    const int lane = threadIdx.x & 31;
    const unsigned gwid = blockIdx.x * WPB + warp;

    // Balanced contiguous partition: warp g owns rays
    // [g*NRAYS/GW, (g+1)*NRAYS/GW) -> 1 ray for most warps, 2 rays for 528
    // warps spread EVENLY across all SMs (no trailing wave, no hot blocks).
    const int rayBeg = (int)((gwid * (unsigned)NRAYS) / (unsigned)GW);
    const int rayEnd = (int)(((gwid + 1u) * (unsigned)NRAYS) / (unsigned)GW);

    float accL1 = 0.f, accL2 = 0.f, accAR = 0.f;

    for (int ray = rayBeg; ray < rayEnd; ray++) {
        // --- per-ray setup ---
        // tindex & pts are independent loads: issue together. origin would be
        // a DEPENDENT load (needs ti) -> load all 5 origins unconditionally
        // (15 floats, uniform, L1-resident) and select via ALU.
        const int   ti  = tindex[ray];
        const float pxr = pts[ray * 3 + 0];
        const float pyr = pts[ray * 3 + 1];
        const float pzr = pts[ray * 3 + 2];

        float oxr = 0.f, oyr = 0.f, ozr = 0.f;
        #pragma unroll
        for (int k = 0; k < 5; k++) {
            const float cx = __ldg(&origin[k * 3 + 0]);
            const float cy = __ldg(&origin[k * 3 + 1]);
            const float cz = __ldg(&origin[k * 3 + 2]);
            if (k == ti) { oxr = cx; oyr = cy; ozr = cz; }
        }

        const float ox = (oxr + 51.2f) * 5.0f;
        const float oy = (oyr + 51.2f) * 5.0f;
        const float oz = (ozr + 3.2f)  * 5.0f;
        const float px = (pxr + 51.2f) * 5.0f;
        const float py = (pyr + 51.2f) * 5.0f;
        const float pz = (pzr + 3.2f)  * 5.0f;

        const float dx = px - ox, dy = py - oy, dz = pz - oz;
        const float gt = sqrtf(dx * dx + dy * dy + dz * dz);
        const float inv = 1.0f / fmaxf(gt, 1e-6f);
        const float ux = dx * inv, uy = dy * inv, uz = dz * inv;

        const float* __restrict__ slice = grid + (size_t)ti * (Zn * Yn * Xn);

        // tau for step at param t (relu'd, 0 if OOB); inb out-param.
        auto sample = [&](float t, bool& inb) -> float {
            const int ix = __float2int_rd(ox + ux * t);
            const int iy = __float2int_rd(oy + uy * t);
            const int iz = __float2int_rd(oz + uz * t);
            inb = ((unsigned)ix < (unsigned)Xn) &
                  ((unsigned)iy < (unsigned)Yn) &
                  ((unsigned)iz < (unsigned)Zn);
            float v = 0.0f;
            if (inb)
                v = fmaxf(__ldg(&slice[((iz * Yn) + iy) * Xn + ix]), 0.0f);
            return v;
        };

        float T     = 1.0f;   // transmittance entering current chunk
        float predL = 0.0f;   // per-lane partial of sum(w * t)

        // 64 steps per iteration, SPLIT layout: lane l owns step base+l and
        // step base+32+l -> each LDG's lanes cover 32 CONSECUTIVE steps.
        // With T_min = 3e-7 (tau_stop ~ 15), ~99% of rays finish in ONE iter.
        for (int base = 0; base < NSTEPS; base += 64) {
            const float ta = (float)(base + lane) + 0.5f;
            const float tb = ta + 32.0f;
            bool inb_a, inb_b;
            const float a = sample(ta, inb_a);   // two independent LDGs
            const float b = sample(tb, inb_b);

            // scan sub-chunk a (steps base..base+31)
            float csa = a;
            #pragma unroll
            for (int off = 1; off < 32; off <<= 1) {
                float v = __shfl_up_sync(0xffffffffu, csa, off);
                if (lane >= off) csa += v;
            }
            const float Sa = __shfl_sync(0xffffffffu, csa, 31);

            // scan sub-chunk b (independent chain; prefix adds Sa at the end)
            float csb = b;
            #pragma unroll
            for (int off = 1; off < 32; off <<= 1) {
                float v = __shfl_up_sync(0xffffffffu, csb, off);
                if (lane >= off) csb += v;
            }

            const float Ea0 = __expf(-(csa - a));        // entering step a
            const float Ea1 = __expf(-csa);              // leaving step a
            const float Eb0 = __expf(-(Sa + csb - b));   // entering step b
            const float Eb1 = __expf(-(Sa + csb));       // leaving step b
            // OOB steps: tau=0 -> adjacent E's equal -> 0 contribution (exact)
            predL += T * ((Ea0 - Ea1) * ta + (Eb0 - Eb1) * tb);

            T *= __shfl_sync(0xffffffffu, Eb1, 31);      // fold chunk total

            const unsigned bal = __ballot_sync(0xffffffffu, inb_b);
            // Exit: last step OOB (convex box => exact) OR T < 3e-7
            // (dropped contribution ~5e-5 m, 4 orders under 1e-3 budget;
            //  R12/R13 measured rel_err ~0 with this bound).
            if (!((bal >> 31) & 1u) || T < 3e-7f) break;
        }

        // butterfly reduction of per-lane pred partials
        #pragma unroll
        for (int off = 16; off; off >>= 1)
            predL += __shfl_xor_sync(0xffffffffu, predL, off);

        // per-ray loss terms (gt >= 0 always -> valid, count = NRAYS)
        const float predm = predL * 0.2f;
        const float gtm   = gt * 0.2f;
        const float diff  = gtm - predm;
        accL1 += fabsf(diff);
        accL2 += diff * diff * 0.5f;
        accAR += __fdividef(fabsf(diff), fmaxf(gtm, 1e-6f));
    }

    // --- per-block reduction across WPB warps (lane-0 scalars) ---
    __shared__ float s1[WPB], s2[WPB], s3[WPB];
    if (lane == 0) { s1[warp] = accL1; s2[warp] = accL2; s3[warp] = accAR; }
    __syncthreads();
    if (threadIdx.x < 32) {
        float a = (lane < WPB) ? s1[lane] : 0.f;
        float b = (lane < WPB) ? s2[lane] : 0.f;
        float d = (lane < WPB) ? s3[lane] : 0.f;
        #pragma unroll
        for (int off = WPB >> 1; off; off >>= 1) {
            a += __shfl_xor_sync(0xffffffffu, a, off);
            b += __shfl_xor_sync(0xffffffffu, b, off);
            d += __shfl_xor_sync(0xffffffffu, d, off);
        }
        if (lane == 0) {
            g_partials[blockIdx.x * 3 + 0] = a;
            g_partials[blockIdx.x * 3 + 1] = b;
            g_partials[blockIdx.x * 3 + 2] = d;
        }
    }

    // --- last-block final reduction ---
    // Release atomic orders the partial stores without a gpu-scope fence
    // (avoids CCTL.IVALL chip-wide L1D flush from __threadfence).
    __shared__ unsigned s_isLast;
    __syncthreads();                     // lane-0 stores of this block done
    if (threadIdx.x == 0) {
        unsigned old;
        asm volatile("atom.release.gpu.global.add.u32 %0, [%1], %2;"
                     : "=r"(old) : "l"(&g_count), "r"(1u) : "memory");
        s_isLast = (old == (unsigned)(NBLK - 1));
    }
    __syncthreads();

    if (s_isLast) {
        // Fixed-order strided sums: deterministic regardless of which block
        // executes this. __ldcg reads at L2 (the coherence point).
        float a = 0.f, b = 0.f, d = 0.f;
        for (int i = threadIdx.x; i < NBLK; i += WPB * 32) {
            a += __ldcg(&g_partials[i * 3 + 0]);
            b += __ldcg(&g_partials[i * 3 + 1]);
            d += __ldcg(&g_partials[i * 3 + 2]);
        }
        #pragma unroll
        for (int off = 16; off; off >>= 1) {
            a += __shfl_xor_sync(0xffffffffu, a, off);
            b += __shfl_xor_sync(0xffffffffu, b, off);
            d += __shfl_xor_sync(0xffffffffu, d, off);
        }
        if (lane == 0) { s1[warp] = a; s2[warp] = b; s3[warp] = d; }
        __syncthreads();
        if (threadIdx.x == 0) {
            float ta = 0.f, tb = 0.f, td = 0.f;
            #pragma unroll
            for (int i = 0; i < WPB; i++) { ta += s1[i]; tb += s2[i]; td += s3[i]; }
            const float cnt = (float)NRAYS;
            out[0] = ta / cnt;
            out[1] = tb / cnt;
            out[2] = td / cnt;
            g_count = 0;                 // reset for next graph replay
        }
    }
}

extern "C" void kernel_launch(void* const* d_in, const int* in_sizes, int n_in,
                              void* d_out, int out_size)
{
    const float* grid   = (const float*)d_in[0];   // (1,5,32,512,512) f32
    const float* origin = (const float*)d_in[1];   // (1,5,3) f32
    const float* pts    = (const float*)d_in[2];   // (1,10000,3) f32
    const int*   tidx   = (const int*)d_in[3];     // (1,10000) i32
    float* out = (float*)d_out;                    // 3 floats

    ray_march_kernel<<<NBLK, WPB * 32>>>(grid, origin, pts, tidx, out);
}

// round 15
// speedup vs baseline: 1.0775x; 1.0775x over previous
#include <cuda_runtime.h>
#include <math.h>

#define NRAYS   10000
#define NSTEPS  768
#define Zn      32
#define Yn      512
#define Xn      512
#define WPB     4                        // warps per block
#define NBLK    1250                     // 4 warps * 1250 = 5000 warps, 2 rays each
#define SLICE   (Zn * Yn * Xn)

// Per-block partial sums [l1, l2, absrel]. Every block writes its slot each
// launch before any reader -> no init needed.
__device__ float    g_partials[NBLK * 3];
__device__ unsigned g_count = 0;         // reset by the last block each launch

__global__ void __launch_bounds__(WPB * 32, 9)   // cap regs so 9 CTAs/SM fit
ray_march_kernel(const float* __restrict__ grid,     // [5,32,512,512] (T,Z,Y,X)
                 const float* __restrict__ origin,   // [5,3]
                 const float* __restrict__ pts,      // [NRAYS,3]
                 const int*   __restrict__ tindex,   // [NRAYS]
                 float*       __restrict__ out)      // [3]
{
    const int warp = threadIdx.x >> 5;
    const int lane = threadIdx.x & 31;
    const int gw   = blockIdx.x * WPB + warp;    // 0..4999
    const int r0   = 2 * gw;                     // two rays per warp, CONCURRENT
    const int r1   = r0 + 1;

    // --- setup for BOTH rays: all loads independent -> one latency round ---
    const int   ti0 = tindex[r0];
    const int   ti1 = tindex[r1];
    const float px0r = pts[r0 * 3 + 0], py0r = pts[r0 * 3 + 1], pz0r = pts[r0 * 3 + 2];
    const float px1r = pts[r1 * 3 + 0], py1r = pts[r1 * 3 + 1], pz1r = pts[r1 * 3 + 2];

    // origin: load all 5 unconditionally (L1-resident), select via ALU
    float o0x = 0.f, o0y = 0.f, o0z = 0.f, o1x = 0.f, o1y = 0.f, o1z = 0.f;
    #pragma unroll
    for (int k = 0; k < 5; k++) {
        const float cx = __ldg(&origin[k * 3 + 0]);
        const float cy = __ldg(&origin[k * 3 + 1]);
        const float cz = __ldg(&origin[k * 3 + 2]);
        if (k == ti0) { o0x = cx; o0y = cy; o0z = cz; }
        if (k == ti1) { o1x = cx; o1y = cy; o1z = cz; }
    }

    const float ox0 = (o0x + 51.2f) * 5.0f, oy0 = (o0y + 51.2f) * 5.0f, oz0 = (o0z + 3.2f) * 5.0f;
    const float ox1 = (o1x + 51.2f) * 5.0f, oy1 = (o1y + 51.2f) * 5.0f, oz1 = (o1z + 3.2f) * 5.0f;
    const float px0 = (px0r + 51.2f) * 5.0f, py0 = (py0r + 51.2f) * 5.0f, pz0 = (pz0r + 3.2f) * 5.0f;
    const float px1 = (px1r + 51.2f) * 5.0f, py1 = (py1r + 51.2f) * 5.0f, pz1 = (pz1r + 3.2f) * 5.0f;

    const float dx0 = px0 - ox0, dy0 = py0 - oy0, dz0 = pz0 - oz0;
    const float dx1 = px1 - ox1, dy1 = py1 - oy1, dz1 = pz1 - oz1;
    const float gt0 = sqrtf(dx0 * dx0 + dy0 * dy0 + dz0 * dz0);
    const float gt1 = sqrtf(dx1 * dx1 + dy1 * dy1 + dz1 * dz1);
    const float iv0 = 1.0f / fmaxf(gt0, 1e-6f);
    const float iv1 = 1.0f / fmaxf(gt1, 1e-6f);
    const float ux0 = dx0 * iv0, uy0 = dy0 * iv0, uz0 = dz0 * iv0;
    const float ux1 = dx1 * iv1, uy1 = dy1 * iv1, uz1 = dz1 * iv1;

    const float* __restrict__ sl0 = grid + (size_t)ti0 * SLICE;
    const float* __restrict__ sl1 = grid + (size_t)ti1 * SLICE;

    float T0 = 1.0f, T1 = 1.0f;       // transmittance entering current chunk
    float pl0 = 0.0f, pl1 = 0.0f;     // per-lane partials of sum(w * t)
    bool  dn0 = false, dn1 = false;

    // 64 steps per iter per ray, interleaved-pair layout: lane l owns steps
    // base+2l and base+2l+1; ONE 5-shfl scan of pair-sums per ray.
    // With T_min = 3e-7 (tau_stop ~ 15), ~99% of rays finish in ONE iter.
    for (int base = 0; base < NSTEPS && !(dn0 && dn1); base += 64) {
        const float ta = (float)(base + 2 * lane) + 0.5f;
        const float tb = ta + 1.0f;

        float a0 = 0.f, b0 = 0.f, a1 = 0.f, b1 = 0.f;
        bool ib0 = false, ib1 = false;
        if (!dn0) {
            { const int ix = __float2int_rd(ox0 + ux0 * ta);
              const int iy = __float2int_rd(oy0 + uy0 * ta);
              const int iz = __float2int_rd(oz0 + uz0 * ta);
              if (((unsigned)ix < (unsigned)Xn) & ((unsigned)iy < (unsigned)Yn) &
                  ((unsigned)iz < (unsigned)Zn))
                  a0 = fmaxf(__ldg(&sl0[((iz * Yn) + iy) * Xn + ix]), 0.0f); }
            { const int ix = __float2int_rd(ox0 + ux0 * tb);
              const int iy = __float2int_rd(oy0 + uy0 * tb);
              const int iz = __float2int_rd(oz0 + uz0 * tb);
              ib0 = ((unsigned)ix < (unsigned)Xn) & ((unsigned)iy < (unsigned)Yn) &
                    ((unsigned)iz < (unsigned)Zn);
              if (ib0)
                  b0 = fmaxf(__ldg(&sl0[((iz * Yn) + iy) * Xn + ix]), 0.0f); }
        }
        if (!dn1) {
            { const int ix = __float2int_rd(ox1 + ux1 * ta);
              const int iy = __float2int_rd(oy1 + uy1 * ta);
              const int iz = __float2int_rd(oz1 + uz1 * ta);
              if (((unsigned)ix < (unsigned)Xn) & ((unsigned)iy < (unsigned)Yn) &
                  ((unsigned)iz < (unsigned)Zn))
                  a1 = fmaxf(__ldg(&sl1[((iz * Yn) + iy) * Xn + ix]), 0.0f); }
            { const int ix = __float2int_rd(ox1 + ux1 * tb);
              const int iy = __float2int_rd(oy1 + uy1 * tb);
              const int iz = __float2int_rd(oz1 + uz1 * tb);
              ib1 = ((unsigned)ix < (unsigned)Xn) & ((unsigned)iy < (unsigned)Yn) &
                    ((unsigned)iz < (unsigned)Zn);
              if (ib1)
                  b1 = fmaxf(__ldg(&sl1[((iz * Yn) + iy) * Xn + ix]), 0.0f); }
        }

        // two independent inclusive scans (all 32 lanes participate always;
        // finished rays carry zeros -> contributions exactly 0, T unchanged)
        const float p0 = a0 + b0;
        const float p1 = a1 + b1;
        float cs0 = p0, cs1 = p1;
        #pragma unroll
        for (int off = 1; off < 32; off <<= 1) {
            const float v0 = __shfl_up_sync(0xffffffffu, cs0, off);
            const float v1 = __shfl_up_sync(0xffffffffu, cs1, off);
            if (lane >= off) { cs0 += v0; cs1 += v1; }
        }
        const float ex0 = cs0 - p0;
        const float ex1 = cs1 - p1;

        const float E00 = __expf(-ex0);          // ray0: entering step a
        const float E01 = __expf(-(ex0 + a0));   //       entering step b
        const float E02 = __expf(-cs0);          //       leaving  step b
        const float E10 = __expf(-ex1);
        const float E11 = __expf(-(ex1 + a1));
        const float E12 = __expf(-cs1);

        pl0 += T0 * ((E00 - E01) * ta + (E01 - E02) * tb);
        pl1 += T1 * ((E10 - E11) * ta + (E11 - E12) * tb);

        T0 *= __shfl_sync(0xffffffffu, E02, 31);
        T1 *= __shfl_sync(0xffffffffu, E12, 31);

        const unsigned bal0 = __ballot_sync(0xffffffffu, ib0);
        const unsigned bal1 = __ballot_sync(0xffffffffu, ib1);
        // Exit per ray: last step OOB (convex box => exact) OR T < 3e-7
        // (dropped contribution ~5e-5 m, 4 orders under the 1e-3 budget;
        //  R12/R13 measured rel_err ~0 with this bound).
        dn0 = dn0 || !((bal0 >> 31) & 1u) || (T0 < 3e-7f);
        dn1 = dn1 || !((bal1 >> 31) & 1u) || (T1 < 3e-7f);
    }

    // butterfly reductions of per-lane pred partials (both rays)
    #pragma unroll
    for (int off = 16; off; off >>= 1) {
        pl0 += __shfl_xor_sync(0xffffffffu, pl0, off);
        pl1 += __shfl_xor_sync(0xffffffffu, pl1, off);
    }

    // --- per-ray loss terms, accumulated over the warp's two rays ---
    const float gm0 = gt0 * 0.2f, gm1 = gt1 * 0.2f;   // >= 0 -> valid, count = NRAYS
    const float d0  = gm0 - pl0 * 0.2f;
    const float d1  = gm1 - pl1 * 0.2f;
    const float accL1 = fabsf(d0) + fabsf(d1);
    const float accL2 = d0 * d0 * 0.5f + d1 * d1 * 0.5f;
    const float accAR = __fdividef(fabsf(d0), fmaxf(gm0, 1e-6f)) +
                        __fdividef(fabsf(d1), fmaxf(gm1, 1e-6f));

    // --- per-block reduction across WPB warps (lane-0 scalars) ---
    __shared__ float s1[WPB], s2[WPB], s3[WPB];
    if (lane == 0) { s1[warp] = accL1; s2[warp] = accL2; s3[warp] = accAR; }
    __syncthreads();
    if (threadIdx.x < 32) {
        float a = (lane < WPB) ? s1[lane] : 0.f;
        float b = (lane < WPB) ? s2[lane] : 0.f;
        float d = (lane < WPB) ? s3[lane] : 0.f;
        #pragma unroll
        for (int off = WPB >> 1; off; off >>= 1) {
            a += __shfl_xor_sync(0xffffffffu, a, off);
            b += __shfl_xor_sync(0xffffffffu, b, off);
            d += __shfl_xor_sync(0xffffffffu, d, off);
        }
        if (lane == 0) {
            g_partials[blockIdx.x * 3 + 0] = a;
            g_partials[blockIdx.x * 3 + 1] = b;
            g_partials[blockIdx.x * 3 + 2] = d;
        }
    }

    // --- last-block final reduction ---
    // Release atomic orders the partial stores without a gpu-scope fence
    // (avoids CCTL.IVALL chip-wide L1D flush from __threadfence).
    __shared__ unsigned s_isLast;
    __syncthreads();                     // lane-0 stores of this block done
    if (threadIdx.x == 0) {
        unsigned old;
        asm volatile("atom.release.gpu.global.add.u32 %0, [%1], %2;"
                     : "=r"(old) : "l"(&g_count), "r"(1u) : "memory");
        s_isLast = (old == (unsigned)(NBLK - 1));
    }
    __syncthreads();

    if (s_isLast) {
        // Fixed-order strided sums: deterministic regardless of which block
        // executes this. __ldcg reads at L2 (the coherence point).
        float a = 0.f, b = 0.f, d = 0.f;
        for (int i = threadIdx.x; i < NBLK; i += WPB * 32) {
            a += __ldcg(&g_partials[i * 3 + 0]);
            b += __ldcg(&g_partials[i * 3 + 1]);
            d += __ldcg(&g_partials[i * 3 + 2]);
        }
        #pragma unroll
        for (int off = 16; off; off >>= 1) {
            a += __shfl_xor_sync(0xffffffffu, a, off);
            b += __shfl_xor_sync(0xffffffffu, b, off);
            d += __shfl_xor_sync(0xffffffffu, d, off);
        }
        if (lane == 0) { s1[warp] = a; s2[warp] = b; s3[warp] = d; }
        __syncthreads();
        if (threadIdx.x == 0) {
            float ta = 0.f, tb = 0.f, td = 0.f;
            #pragma unroll
            for (int i = 0; i < WPB; i++) { ta += s1[i]; tb += s2[i]; td += s3[i]; }
            const float cnt = (float)NRAYS;
            out[0] = ta / cnt;
            out[1] = tb / cnt;
            out[2] = td / cnt;
            g_count = 0;                 // reset for next graph replay
        }
    }
}

extern "C" void kernel_launch(void* const* d_in, const int* in_sizes, int n_in,
                              void* d_out, int out_size)
{
    const float* grid   = (const float*)d_in[0];   // (1,5,32,512,512) f32
    const float* origin = (const float*)d_in[1];   // (1,5,3) f32
    const float* pts    = (const float*)d_in[2];   // (1,10000,3) f32
    const int*   tidx   = (const int*)d_in[3];     // (1,10000) i32
    float* out = (float*)d_out;                    // 3 floats

    ray_march_kernel<<<NBLK, WPB * 32>>>(grid, origin, pts, tidx, out);
}